// round 6
// baseline (speedup 1.0000x reference)
#include <cuda_runtime.h>
#include <cuda_bf16.h>
#include <cstdint>

#define NN   50000
#define NE   800000
#define NR   8
#define DIM  256
#define MPAD 50048          // 391 * 128
#define MTILES 391

// GEMM tiling
#define BK        32
#define STAGES    3
#define ROWPITCH  80                 // bytes per smem row: 32 bf16 (64B) + 16B pad
#define AREA      (128 * ROWPITCH)   // 10240 B per operand tile
#define STAGE_BYTES (4 * AREA)       // Ah, Al, Bh, Bl
#define GEMM_SMEM (STAGES * STAGE_BYTES)   // 122880

// ---------------- scratch (__device__ globals; no allocation allowed) ----------------
__device__ __align__(256) float          g_xt[NR * MPAD * DIM];     // 410 MB
__device__ __align__(256) float          g_h [MPAD * DIM];          // 51 MB
__device__ __align__(256) __nv_bfloat16  g_ahi[MPAD * DIM];
__device__ __align__(256) __nv_bfloat16  g_alo[MPAD * DIM];
__device__ __align__(256) __nv_bfloat16  g_bt0h[NR * DIM * DIM];
__device__ __align__(256) __nv_bfloat16  g_bt0l[NR * DIM * DIM];
__device__ __align__(256) __nv_bfloat16  g_bt1h[NR * DIM * DIM];
__device__ __align__(256) __nv_bfloat16  g_bt1l[NR * DIM * DIM];
__device__ int       g_cnt[NN + 1];
__device__ int       g_off[NN + 1];
__device__ int       g_cur[NN];
__device__ unsigned  g_pack[NE];
__device__ int       g_is64_idx;
__device__ int       g_is64_typ;

// ---------------- PTX helpers (base-target only: no tcgen05!) ----------------
__device__ __forceinline__ uint32_t smem_u32(const void* p) {
    uint32_t a;
    asm("{ .reg .u64 t; cvta.to.shared.u64 t, %1; cvt.u32.u64 %0, t; }" : "=r"(a) : "l"(p));
    return a;
}
__device__ __forceinline__ void cp16(uint32_t dst, const void* src) {
    asm volatile("cp.async.cg.shared.global [%0], [%1], 16;" :: "r"(dst), "l"(src) : "memory");
}
__device__ __forceinline__ void cp_commit() {
    asm volatile("cp.async.commit_group;" ::: "memory");
}
__device__ __forceinline__ void cp_wait1() {
    asm volatile("cp.async.wait_group 1;" ::: "memory");
}
__device__ __forceinline__ void ldsm4(uint32_t* r, uint32_t addr) {
    asm volatile("ldmatrix.sync.aligned.m8n8.x4.shared.b16 {%0,%1,%2,%3}, [%4];"
                 : "=r"(r[0]), "=r"(r[1]), "=r"(r[2]), "=r"(r[3]) : "r"(addr));
}
__device__ __forceinline__ void mma16816(float* d, const uint32_t* a, const uint32_t* b) {
    asm volatile("mma.sync.aligned.m16n8k16.row.col.f32.bf16.bf16.f32 "
                 "{%0,%1,%2,%3}, {%4,%5,%6,%7}, {%8,%9}, {%0,%1,%2,%3};"
                 : "+f"(d[0]), "+f"(d[1]), "+f"(d[2]), "+f"(d[3])
                 : "r"(a[0]), "r"(a[1]), "r"(a[2]), "r"(a[3]), "r"(b[0]), "r"(b[1]));
}

// ---------------- dtype detection (int64 vs int32 for indices) ----------------
__global__ void detect_kernel(const int* eidx, const int* etyp) {
    if (threadIdx.x == 0 && blockIdx.x == 0) {
        int ok_i = 1, ok_t = 1;
        for (int k = 0; k < 16; k++) {
            if (eidx[2 * k + 1] != 0) ok_i = 0;
            if (etyp[2 * k + 1] != 0) ok_t = 0;
        }
        g_is64_idx = ok_i;
        g_is64_typ = ok_t;
    }
}
__device__ __forceinline__ int ld_idx(const void* p, int i, int is64) {
    return is64 ? (int)((const long long*)p)[i] : ((const int*)p)[i];
}

// ---------------- prep: split x (or h) into bf16 hi/lo with zero padding ----------------
__global__ void split_kernel(const float* __restrict__ src, int from_h) {
    const float* s = from_h ? g_h : src;
    size_t i = (size_t)blockIdx.x * blockDim.x + threadIdx.x;
    if (i >= (size_t)MPAD * DIM) return;
    float v = (i < (size_t)NN * DIM) ? s[i] : 0.0f;
    __nv_bfloat16 h = __float2bfloat16(v);
    g_ahi[i] = h;
    g_alo[i] = __float2bfloat16(v - __bfloat162float(h));
}

// ---------------- prep: transpose + split W[r,k,n] -> Bt[r,n,k] hi/lo ----------------
__global__ void prep_w_kernel(const float* __restrict__ W0, const float* __restrict__ W1) {
    int idx = blockIdx.x * blockDim.x + threadIdx.x;
    if (idx >= NR * DIM * DIM) return;
    int r = idx >> 16, n = (idx >> 8) & 255, k = idx & 255;
    size_t s = ((size_t)r << 16) + (size_t)k * DIM + n;
    float w0 = W0[s];
    __nv_bfloat16 h0 = __float2bfloat16(w0);
    g_bt0h[idx] = h0;
    g_bt0l[idx] = __float2bfloat16(w0 - __bfloat162float(h0));
    float w1 = W1[s];
    __nv_bfloat16 h1 = __float2bfloat16(w1);
    g_bt1h[idx] = h1;
    g_bt1l[idx] = __float2bfloat16(w1 - __bfloat162float(h1));
}

// ---------------- CSR build ----------------
__global__ void zero_cnt_kernel() {
    int i = blockIdx.x * blockDim.x + threadIdx.x;
    if (i <= NN) g_cnt[i] = 0;
}
__global__ void hist_kernel(const void* eidx) {
    int e = blockIdx.x * blockDim.x + threadIdx.x;
    if (e >= NE) return;
    int dst = ld_idx(eidx, NE + e, g_is64_idx);
    atomicAdd(&g_cnt[dst], 1);
}
__global__ void scan_kernel() {
    __shared__ int s[1024];
    __shared__ int carry_s;
    int t = threadIdx.x;
    if (t == 0) carry_s = 0;
    __syncthreads();
    for (int base = 0; base < NN + 1; base += 1024) {
        int idx = base + t;
        int v = (idx < NN) ? g_cnt[idx] : 0;
        s[t] = v;
        __syncthreads();
        int acc = v;
        for (int o = 1; o < 1024; o <<= 1) {
            int add = (t >= o) ? s[t - o] : 0;
            __syncthreads();
            acc += add;
            s[t] = acc;
            __syncthreads();
        }
        int outv = carry_s + acc - v;  // exclusive
        if (idx <= NN) {
            g_off[idx] = outv;
            if (idx < NN) g_cur[idx] = outv;
        }
        __syncthreads();
        if (t == 1023) carry_s += acc;
        __syncthreads();
    }
}
__global__ void fill_kernel(const void* eidx, const void* etyp) {
    int e = blockIdx.x * blockDim.x + threadIdx.x;
    if (e >= NE) return;
    int is64i = g_is64_idx;
    int src = ld_idx(eidx, e, is64i);
    int dst = ld_idx(eidx, NE + e, is64i);
    int rel = ld_idx(etyp, e, g_is64_typ);
    int pos = atomicAdd(&g_cur[dst], 1);
    g_pack[pos] = (unsigned)src | ((unsigned)rel << 16);
}

// ---------------- GEMM: XT[r] = X @ W[r]  (mma.sync bf16, hi/lo 3-term split) ----------------
// grid (MTILES, 2, NR), 256 threads = 8 warps in 4(m) x 2(n). CTA tile 128x128, K=256.
__global__ __launch_bounds__(256, 1) void gemm_kernel(int layer) {
    extern __shared__ char dyn[];
    const int tid  = threadIdx.x;
    const int lane = tid & 31, warp = tid >> 5;
    const int wm = warp >> 1, wn = warp & 1;
    const int mbase = blockIdx.x * 128;
    const int nbase = blockIdx.y * 128;
    const int rel   = blockIdx.z;

    const __nv_bfloat16* Bh = (layer ? g_bt1h : g_bt0h) + ((size_t)rel << 16) + (size_t)nbase * DIM;
    const __nv_bfloat16* Bl = (layer ? g_bt1l : g_bt0l) + ((size_t)rel << 16) + (size_t)nbase * DIM;
    const __nv_bfloat16* Ah = g_ahi + (size_t)mbase * DIM;
    const __nv_bfloat16* Al = g_alo + (size_t)mbase * DIM;

    const uint32_t sbase = smem_u32(dyn);

    float acc[2][8][4];
    #pragma unroll
    for (int i = 0; i < 2; i++)
        #pragma unroll
        for (int j = 0; j < 8; j++)
            #pragma unroll
            for (int q = 0; q < 4; q++) acc[i][j][q] = 0.f;

    // stage loader: Ah | Al | Bh | Bl, 128 rows x 32 bf16 each, 16B chunks
    auto load_stage = [&](int buf, int k0) {
        uint32_t sb = sbase + buf * STAGE_BYTES;
        const __nv_bfloat16* srcs[4] = { Ah, Al, Bh, Bl };
        #pragma unroll
        for (int arr = 0; arr < 4; arr++) {
            #pragma unroll
            for (int half = 0; half < 2; half++) {
                int rem = tid + half * 256;      // 0..511
                int row = rem >> 2, seg = rem & 3;
                cp16(sb + arr * AREA + row * ROWPITCH + seg * 16,
                     srcs[arr] + (size_t)row * DIM + k0 + seg * 8);
            }
        }
    };

    load_stage(0, 0);  cp_commit();
    load_stage(1, BK); cp_commit();

    for (int s = 0; s < 8; s++) {
        cp_wait1();
        __syncthreads();
        if (s + 2 < 8) load_stage((s + 2) % STAGES, (s + 2) * BK);
        cp_commit();

        uint32_t sb = sbase + (s % STAGES) * STAGE_BYTES;
        #pragma unroll
        for (int k16 = 0; k16 < 2; k16++) {
            uint32_t af[2][2][4];
            uint32_t bf[2][8][2];
            #pragma unroll
            for (int hl = 0; hl < 2; hl++) {
                uint32_t abase = sb + hl * AREA;
                #pragma unroll
                for (int mt = 0; mt < 2; mt++) {
                    int m_local = wm * 32 + mt * 16 + (lane & 15);
                    ldsm4(af[hl][mt], abase + m_local * ROWPITCH + k16 * 32 + (lane >> 4) * 16);
                }
                uint32_t bbase = sb + (2 + hl) * AREA;
                #pragma unroll
                for (int np = 0; np < 4; np++) {
                    int n_local = wn * 64 + np * 16 + ((lane >> 4) << 3) + (lane & 7);
                    int khalf = (lane >> 3) & 1;
                    ldsm4(&bf[hl][np * 2][0], bbase + n_local * ROWPITCH + k16 * 32 + khalf * 16);
                }
            }
            #pragma unroll
            for (int mt = 0; mt < 2; mt++)
                #pragma unroll
                for (int nt = 0; nt < 8; nt++) {
                    mma16816(acc[mt][nt], af[0][mt], bf[0][nt]);  // Ah*Bh
                    mma16816(acc[mt][nt], af[0][mt], bf[1][nt]);  // Ah*Bl
                    mma16816(acc[mt][nt], af[1][mt], bf[0][nt]);  // Al*Bh
                }
        }
        // next iteration's top-of-loop __syncthreads protects buffer reuse
    }

    // epilogue: write fp32 tile to g_xt[rel]
    #pragma unroll
    for (int mt = 0; mt < 2; mt++) {
        int gm = mbase + wm * 32 + mt * 16 + (lane >> 2);
        float* rowp = g_xt + ((size_t)rel * MPAD + gm) * DIM + nbase + wn * 64 + 2 * (lane & 3);
        #pragma unroll
        for (int nt = 0; nt < 8; nt++) {
            *reinterpret_cast<float2*>(rowp + nt * 8) =
                make_float2(acc[mt][nt][0], acc[mt][nt][1]);
            *reinterpret_cast<float2*>(rowp + 8 * DIM + nt * 8) =
                make_float2(acc[mt][nt][2], acc[mt][nt][3]);
        }
    }
}

// ---------------- edge aggregation: out[dst] = sum relu(XT[rel,src] + b) ----------------
// 256 threads = 4 groups of 64; one dst per group; float4 per lane (256 cols).
__global__ __launch_bounds__(256) void edge_kernel(const float* __restrict__ bias,
                                                   float* __restrict__ out_arg) {
    float* outp = out_arg ? out_arg : g_h;
    int g = threadIdx.x >> 6;
    int lane = threadIdx.x & 63;
    int dst = blockIdx.x * 4 + g;
    if (dst >= NN) return;

    float4 bb = reinterpret_cast<const float4*>(bias)[lane];
    float4 acc = make_float4(0.f, 0.f, 0.f, 0.f);
    int s = g_off[dst], e = g_off[dst + 1];
    const float4* xt4 = reinterpret_cast<const float4*>(g_xt);

    int i = s;
    for (; i + 1 < e; i += 2) {
        unsigned p0 = __ldg(&g_pack[i]);
        unsigned p1 = __ldg(&g_pack[i + 1]);
        size_t r0 = ((size_t)(p0 >> 16) * MPAD + (p0 & 0xFFFFu)) * 64 + lane;
        size_t r1 = ((size_t)(p1 >> 16) * MPAD + (p1 & 0xFFFFu)) * 64 + lane;
        float4 v0 = __ldg(&xt4[r0]);
        float4 v1 = __ldg(&xt4[r1]);
        acc.x += fmaxf(v0.x + bb.x, 0.f) + fmaxf(v1.x + bb.x, 0.f);
        acc.y += fmaxf(v0.y + bb.y, 0.f) + fmaxf(v1.y + bb.y, 0.f);
        acc.z += fmaxf(v0.z + bb.z, 0.f) + fmaxf(v1.z + bb.z, 0.f);
        acc.w += fmaxf(v0.w + bb.w, 0.f) + fmaxf(v1.w + bb.w, 0.f);
    }
    if (i < e) {
        unsigned p0 = __ldg(&g_pack[i]);
        size_t r0 = ((size_t)(p0 >> 16) * MPAD + (p0 & 0xFFFFu)) * 64 + lane;
        float4 v0 = __ldg(&xt4[r0]);
        acc.x += fmaxf(v0.x + bb.x, 0.f);
        acc.y += fmaxf(v0.y + bb.y, 0.f);
        acc.z += fmaxf(v0.z + bb.z, 0.f);
        acc.w += fmaxf(v0.w + bb.w, 0.f);
    }
    reinterpret_cast<float4*>(outp)[(size_t)dst * 64 + lane] = acc;
}

// ---------------- launch ----------------
extern "C" void kernel_launch(void* const* d_in, const int* in_sizes, int n_in,
                              void* d_out, int out_size) {
    const float* x  = (const float*)d_in[0];
    const float* W0 = (const float*)d_in[1];
    const float* b0 = (const float*)d_in[2];
    const float* W1 = (const float*)d_in[3];
    const float* b1 = (const float*)d_in[4];
    const void*  ei = d_in[5];
    const void*  et = d_in[6];
    float* out = (float*)d_out;

    cudaFuncSetAttribute(gemm_kernel, cudaFuncAttributeMaxDynamicSharedMemorySize, GEMM_SMEM);

    detect_kernel<<<1, 32>>>((const int*)ei, (const int*)et);

    int split_blocks = (MPAD * DIM + 255) / 256;
    split_kernel<<<split_blocks, 256>>>(x, 0);
    prep_w_kernel<<<(NR * DIM * DIM + 255) / 256, 256>>>(W0, W1);

    zero_cnt_kernel<<<(NN + 256) / 256, 256>>>();
    hist_kernel<<<(NE + 255) / 256, 256>>>(ei);
    scan_kernel<<<1, 1024>>>();
    fill_kernel<<<(NE + 255) / 256, 256>>>(ei, et);

    // layer 1
    gemm_kernel<<<dim3(MTILES, 2, NR), 256, GEMM_SMEM>>>(0);
    edge_kernel<<<(NN + 3) / 4, 256>>>(b0, nullptr);   // -> g_h

    // layer 2
    split_kernel<<<split_blocks, 256>>>(nullptr, 1);   // g_h -> hi/lo
    gemm_kernel<<<dim3(MTILES, 2, NR), 256, GEMM_SMEM>>>(1);
    edge_kernel<<<(NN + 3) / 4, 256>>>(b1, out);
}

// round 7
// speedup vs baseline: 1.3575x; 1.3575x over previous
#include <cuda_runtime.h>
#include <cuda_bf16.h>
#include <cuda_fp16.h>
#include <cstdint>

#define NN   50000
#define NE   800000
#define NR   8
#define DIM  256
#define MPAD 50048          // 391 * 128
#define MTILES 391

// GEMM tiling
#define BK        32
#define STAGES    3
#define ROWPITCH  80                 // bytes per smem row: 32 fp16 (64B) + 16B pad
#define AREA      (128 * ROWPITCH)   // 10240 B per operand tile
#define STAGE_BYTES (3 * AREA)       // Ah, Al, Bh
#define GEMM_SMEM (STAGES * STAGE_BYTES)   // 92160

// ---------------- scratch (__device__ globals; no allocation allowed) ----------------
__device__ __align__(256) float   g_xt[NR * MPAD * DIM];     // 410 MB
__device__ __align__(256) float   g_h [MPAD * DIM];          // 51 MB
__device__ __align__(256) __half  g_ahi[MPAD * DIM];
__device__ __align__(256) __half  g_alo[MPAD * DIM];
__device__ __align__(256) __half  g_bt0h[NR * DIM * DIM];
__device__ __align__(256) __half  g_bt1h[NR * DIM * DIM];
__device__ int       g_cnt[NN + 1];
__device__ int       g_off[NN + 1];
__device__ int       g_cur[NN];
__device__ unsigned  g_pack[NE];
__device__ int       g_is64_idx;
__device__ int       g_is64_typ;

// ---------------- PTX helpers (base-target only: no tcgen05!) ----------------
__device__ __forceinline__ uint32_t smem_u32(const void* p) {
    uint32_t a;
    asm("{ .reg .u64 t; cvta.to.shared.u64 t, %1; cvt.u32.u64 %0, t; }" : "=r"(a) : "l"(p));
    return a;
}
__device__ __forceinline__ void cp16(uint32_t dst, const void* src) {
    asm volatile("cp.async.cg.shared.global [%0], [%1], 16;" :: "r"(dst), "l"(src) : "memory");
}
__device__ __forceinline__ void cp_commit() {
    asm volatile("cp.async.commit_group;" ::: "memory");
}
__device__ __forceinline__ void cp_wait1() {
    asm volatile("cp.async.wait_group 1;" ::: "memory");
}
__device__ __forceinline__ void ldsm4(uint32_t* r, uint32_t addr) {
    asm volatile("ldmatrix.sync.aligned.m8n8.x4.shared.b16 {%0,%1,%2,%3}, [%4];"
                 : "=r"(r[0]), "=r"(r[1]), "=r"(r[2]), "=r"(r[3]) : "r"(addr));
}
__device__ __forceinline__ void mma16816(float* d, const uint32_t* a, const uint32_t* b) {
    asm volatile("mma.sync.aligned.m16n8k16.row.col.f32.f16.f16.f32 "
                 "{%0,%1,%2,%3}, {%4,%5,%6,%7}, {%8,%9}, {%0,%1,%2,%3};"
                 : "+f"(d[0]), "+f"(d[1]), "+f"(d[2]), "+f"(d[3])
                 : "r"(a[0]), "r"(a[1]), "r"(a[2]), "r"(a[3]), "r"(b[0]), "r"(b[1]));
}

// ---------------- dtype detection (int64 vs int32 for indices) ----------------
__global__ void detect_kernel(const int* eidx, const int* etyp) {
    if (threadIdx.x == 0 && blockIdx.x == 0) {
        int ok_i = 1, ok_t = 1;
        for (int k = 0; k < 16; k++) {
            if (eidx[2 * k + 1] != 0) ok_i = 0;
            if (etyp[2 * k + 1] != 0) ok_t = 0;
        }
        g_is64_idx = ok_i;
        g_is64_typ = ok_t;
    }
}
__device__ __forceinline__ int ld_idx(const void* p, int i, int is64) {
    return is64 ? (int)((const long long*)p)[i] : ((const int*)p)[i];
}

// ---------------- prep: split x (or h) into fp16 hi/lo with zero padding ----------------
__global__ void split_kernel(const float* __restrict__ src, int from_h) {
    const float* s = from_h ? g_h : src;
    size_t i = (size_t)blockIdx.x * blockDim.x + threadIdx.x;
    if (i >= (size_t)MPAD * DIM) return;
    float v = (i < (size_t)NN * DIM) ? s[i] : 0.0f;
    __half h = __float2half_rn(v);
    g_ahi[i] = h;
    g_alo[i] = __float2half_rn(v - __half2float(h));
}

// ---------------- prep: transpose W[r,k,n] -> Bt[r,n,k] fp16 ----------------
__global__ void prep_w_kernel(const float* __restrict__ W0, const float* __restrict__ W1) {
    int idx = blockIdx.x * blockDim.x + threadIdx.x;
    if (idx >= NR * DIM * DIM) return;
    int r = idx >> 16, n = (idx >> 8) & 255, k = idx & 255;
    size_t s = ((size_t)r << 16) + (size_t)k * DIM + n;
    g_bt0h[idx] = __float2half_rn(W0[s]);
    g_bt1h[idx] = __float2half_rn(W1[s]);
}

// ---------------- CSR build ----------------
__global__ void zero_cnt_kernel() {
    int i = blockIdx.x * blockDim.x + threadIdx.x;
    if (i <= NN) g_cnt[i] = 0;
}
__global__ void hist_kernel(const void* eidx) {
    int e = blockIdx.x * blockDim.x + threadIdx.x;
    if (e >= NE) return;
    int dst = ld_idx(eidx, NE + e, g_is64_idx);
    atomicAdd(&g_cnt[dst], 1);
}
// thread-serial + single 1024-wide block scan
__global__ void scan_kernel() {
    __shared__ int part[1024];
    const int t = threadIdx.x;
    const int PER = (NN + 1023) / 1024;   // 49
    const int base = t * PER;
    int sum = 0;
    #pragma unroll 7
    for (int i = 0; i < PER; i++) {
        int idx = base + i;
        if (idx < NN) sum += g_cnt[idx];
    }
    part[t] = sum;
    __syncthreads();
    int acc = sum;
    for (int o = 1; o < 1024; o <<= 1) {
        int add = (t >= o) ? part[t - o] : 0;
        __syncthreads();
        acc += add;
        part[t] = acc;
        __syncthreads();
    }
    int run = acc - sum;   // exclusive prefix of this thread's chunk
    for (int i = 0; i < PER; i++) {
        int idx = base + i;
        if (idx > NN) break;
        if (idx == NN) { g_off[NN] = run; break; }
        g_off[idx] = run;
        g_cur[idx] = run;
        run += g_cnt[idx];
    }
}
__global__ void fill_kernel(const void* eidx, const void* etyp) {
    int e = blockIdx.x * blockDim.x + threadIdx.x;
    if (e >= NE) return;
    int is64i = g_is64_idx;
    int src = ld_idx(eidx, e, is64i);
    int dst = ld_idx(eidx, NE + e, is64i);
    int rel = ld_idx(etyp, e, g_is64_typ);
    int pos = atomicAdd(&g_cur[dst], 1);
    g_pack[pos] = (unsigned)src | ((unsigned)rel << 16);
}

// ---------------- GEMM: XT[r] = X @ W[r]  (mma.sync fp16, hi/lo 2-term split) ----------------
// grid (MTILES, 2, NR), 256 threads = 8 warps in 4(m) x 2(n). CTA tile 128x128, K=256.
__global__ __launch_bounds__(256, 1) void gemm_kernel(int layer) {
    extern __shared__ char dyn[];
    const int tid  = threadIdx.x;
    const int lane = tid & 31, warp = tid >> 5;
    const int wm = warp >> 1, wn = warp & 1;
    const int mbase = blockIdx.x * 128;
    const int nbase = blockIdx.y * 128;
    const int rel   = blockIdx.z;

    const __half* Bh = (layer ? g_bt1h : g_bt0h) + ((size_t)rel << 16) + (size_t)nbase * DIM;
    const __half* Ah = g_ahi + (size_t)mbase * DIM;
    const __half* Al = g_alo + (size_t)mbase * DIM;

    const uint32_t sbase = smem_u32(dyn);

    float acc[2][8][4];
    #pragma unroll
    for (int i = 0; i < 2; i++)
        #pragma unroll
        for (int j = 0; j < 8; j++)
            #pragma unroll
            for (int q = 0; q < 4; q++) acc[i][j][q] = 0.f;

    // stage loader: Ah | Al | Bh, 128 rows x 32 fp16 each, 16B chunks
    auto load_stage = [&](int buf, int k0) {
        uint32_t sb = sbase + buf * STAGE_BYTES;
        const __half* srcs[3] = { Ah, Al, Bh };
        #pragma unroll
        for (int arr = 0; arr < 3; arr++) {
            #pragma unroll
            for (int half = 0; half < 2; half++) {
                int rem = tid + half * 256;      // 0..511
                int row = rem >> 2, seg = rem & 3;
                cp16(sb + arr * AREA + row * ROWPITCH + seg * 16,
                     srcs[arr] + (size_t)row * DIM + k0 + seg * 8);
            }
        }
    };

    load_stage(0, 0);  cp_commit();
    load_stage(1, BK); cp_commit();

    for (int s = 0; s < 8; s++) {
        cp_wait1();
        __syncthreads();
        if (s + 2 < 8) load_stage((s + 2) % STAGES, (s + 2) * BK);
        cp_commit();

        uint32_t sb = sbase + (s % STAGES) * STAGE_BYTES;
        #pragma unroll
        for (int k16 = 0; k16 < 2; k16++) {
            uint32_t af[2][2][4];   // [hl][mt]
            uint32_t bf[8][2];
            #pragma unroll
            for (int hl = 0; hl < 2; hl++) {
                uint32_t abase = sb + hl * AREA;
                #pragma unroll
                for (int mt = 0; mt < 2; mt++) {
                    int m_local = wm * 32 + mt * 16 + (lane & 15);
                    ldsm4(af[hl][mt], abase + m_local * ROWPITCH + k16 * 32 + (lane >> 4) * 16);
                }
            }
            {
                uint32_t bbase = sb + 2 * AREA;
                #pragma unroll
                for (int np = 0; np < 4; np++) {
                    int n_local = wn * 64 + np * 16 + ((lane >> 4) << 3) + (lane & 7);
                    int khalf = (lane >> 3) & 1;
                    ldsm4(&bf[np * 2][0], bbase + n_local * ROWPITCH + k16 * 32 + khalf * 16);
                }
            }
            #pragma unroll
            for (int mt = 0; mt < 2; mt++)
                #pragma unroll
                for (int nt = 0; nt < 8; nt++) {
                    mma16816(acc[mt][nt], af[0][mt], bf[nt]);  // Ah*Bh
                    mma16816(acc[mt][nt], af[1][mt], bf[nt]);  // Al*Bh
                }
        }
        // next iteration's top-of-loop __syncthreads protects buffer reuse
    }

    // epilogue: write fp32 tile to g_xt[rel]
    #pragma unroll
    for (int mt = 0; mt < 2; mt++) {
        int gm = mbase + wm * 32 + mt * 16 + (lane >> 2);
        float* rowp = g_xt + ((size_t)rel * MPAD + gm) * DIM + nbase + wn * 64 + 2 * (lane & 3);
        #pragma unroll
        for (int nt = 0; nt < 8; nt++) {
            *reinterpret_cast<float2*>(rowp + nt * 8) =
                make_float2(acc[mt][nt][0], acc[mt][nt][1]);
            *reinterpret_cast<float2*>(rowp + 8 * DIM + nt * 8) =
                make_float2(acc[mt][nt][2], acc[mt][nt][3]);
        }
    }
}

// ---------------- edge aggregation: out[dst] = sum relu(XT[rel,src] + b) ----------------
// 256 threads = 4 groups of 64; one dst per group; float4 per lane (256 cols).
__global__ __launch_bounds__(256) void edge_kernel(const float* __restrict__ bias,
                                                   float* __restrict__ out_arg) {
    float* outp = out_arg ? out_arg : g_h;
    int g = threadIdx.x >> 6;
    int lane = threadIdx.x & 63;
    int dst = blockIdx.x * 4 + g;
    if (dst >= NN) return;

    float4 bb = reinterpret_cast<const float4*>(bias)[lane];
    float4 acc = make_float4(0.f, 0.f, 0.f, 0.f);
    int s = g_off[dst], e = g_off[dst + 1];
    const float4* xt4 = reinterpret_cast<const float4*>(g_xt);

    int i = s;
    for (; i + 3 < e; i += 4) {
        unsigned p0 = __ldg(&g_pack[i]);
        unsigned p1 = __ldg(&g_pack[i + 1]);
        unsigned p2 = __ldg(&g_pack[i + 2]);
        unsigned p3 = __ldg(&g_pack[i + 3]);
        size_t r0 = ((size_t)(p0 >> 16) * MPAD + (p0 & 0xFFFFu)) * 64 + lane;
        size_t r1 = ((size_t)(p1 >> 16) * MPAD + (p1 & 0xFFFFu)) * 64 + lane;
        size_t r2 = ((size_t)(p2 >> 16) * MPAD + (p2 & 0xFFFFu)) * 64 + lane;
        size_t r3 = ((size_t)(p3 >> 16) * MPAD + (p3 & 0xFFFFu)) * 64 + lane;
        float4 v0 = __ldg(&xt4[r0]);
        float4 v1 = __ldg(&xt4[r1]);
        float4 v2 = __ldg(&xt4[r2]);
        float4 v3 = __ldg(&xt4[r3]);
        acc.x += fmaxf(v0.x + bb.x, 0.f) + fmaxf(v1.x + bb.x, 0.f)
               + fmaxf(v2.x + bb.x, 0.f) + fmaxf(v3.x + bb.x, 0.f);
        acc.y += fmaxf(v0.y + bb.y, 0.f) + fmaxf(v1.y + bb.y, 0.f)
               + fmaxf(v2.y + bb.y, 0.f) + fmaxf(v3.y + bb.y, 0.f);
        acc.z += fmaxf(v0.z + bb.z, 0.f) + fmaxf(v1.z + bb.z, 0.f)
               + fmaxf(v2.z + bb.z, 0.f) + fmaxf(v3.z + bb.z, 0.f);
        acc.w += fmaxf(v0.w + bb.w, 0.f) + fmaxf(v1.w + bb.w, 0.f)
               + fmaxf(v2.w + bb.w, 0.f) + fmaxf(v3.w + bb.w, 0.f);
    }
    for (; i < e; i++) {
        unsigned p0 = __ldg(&g_pack[i]);
        size_t r0 = ((size_t)(p0 >> 16) * MPAD + (p0 & 0xFFFFu)) * 64 + lane;
        float4 v0 = __ldg(&xt4[r0]);
        acc.x += fmaxf(v0.x + bb.x, 0.f);
        acc.y += fmaxf(v0.y + bb.y, 0.f);
        acc.z += fmaxf(v0.z + bb.z, 0.f);
        acc.w += fmaxf(v0.w + bb.w, 0.f);
    }
    reinterpret_cast<float4*>(outp)[(size_t)dst * 64 + lane] = acc;
}

// ---------------- launch ----------------
extern "C" void kernel_launch(void* const* d_in, const int* in_sizes, int n_in,
                              void* d_out, int out_size) {
    const float* x  = (const float*)d_in[0];
    const float* W0 = (const float*)d_in[1];
    const float* b0 = (const float*)d_in[2];
    const float* W1 = (const float*)d_in[3];
    const float* b1 = (const float*)d_in[4];
    const void*  ei = d_in[5];
    const void*  et = d_in[6];
    float* out = (float*)d_out;

    cudaFuncSetAttribute(gemm_kernel, cudaFuncAttributeMaxDynamicSharedMemorySize, GEMM_SMEM);

    int split_blocks = (MPAD * DIM + 255) / 256;

    // Order chosen so the layer-0 GEMM sits in the ncu -s 5 -c 1 window
    detect_kernel<<<1, 32>>>((const int*)ei, (const int*)et);            // 1
    split_kernel<<<split_blocks, 256>>>(x, 0);                           // 2
    prep_w_kernel<<<(NR * DIM * DIM + 255) / 256, 256>>>(W0, W1);        // 3
    gemm_kernel<<<dim3(MTILES, 2, NR), 256, GEMM_SMEM>>>(0);             // 4  <- profiled
    zero_cnt_kernel<<<(NN + 256) / 256, 256>>>();                        // 5
    hist_kernel<<<(NE + 255) / 256, 256>>>(ei);                          // 6
    scan_kernel<<<1, 1024>>>();                                          // 7
    fill_kernel<<<(NE + 255) / 256, 256>>>(ei, et);                      // 8

    edge_kernel<<<(NN + 3) / 4, 256>>>(b0, nullptr);                     // -> g_h

    // layer 2
    split_kernel<<<split_blocks, 256>>>(nullptr, 1);                     // g_h -> hi/lo
    gemm_kernel<<<dim3(MTILES, 2, NR), 256, GEMM_SMEM>>>(1);
    edge_kernel<<<(NN + 3) / 4, 256>>>(b1, out);
}

// round 9
// speedup vs baseline: 2.3149x; 1.7053x over previous
#include <cuda_runtime.h>
#include <cuda_fp16.h>
#include <cstdint>

#define NN   50000
#define NE   800000
#define NR   8
#define DIM  256
#define MPAD 50048          // 391 * 128
#define MTILES 391

// GEMM tiling
#define BK        32
#define STAGES    3
#define ROWPITCH  80                 // bytes per smem row: 32 fp16 (64B) + 16B pad
#define AREA      (128 * ROWPITCH)   // 10240 B per operand tile
#define STAGE_BYTES (2 * AREA)       // A, B
#define GEMM_SMEM (STAGES * STAGE_BYTES)   // 61440

// ---------------- scratch (__device__ globals; no allocation allowed) ----------------
__device__ __align__(256) __half  g_xt[NR * MPAD * DIM];     // 205 MB
__device__ __align__(256) __half  g_ah[MPAD * DIM];          // GEMM A input (x, then h)
__device__ __align__(256) __half  g_bt0[NR * DIM * DIM];
__device__ __align__(256) __half  g_bt1[NR * DIM * DIM];
__device__ int       g_cnt[NN + 1];
__device__ int       g_off[NN + 1];
__device__ int       g_cur[NN];
__device__ unsigned  g_pack[NE];
__device__ int       g_is64_idx;
__device__ int       g_is64_typ;

// ---------------- PTX helpers (base-target only) ----------------
__device__ __forceinline__ uint32_t smem_u32(const void* p) {
    uint32_t a;
    asm("{ .reg .u64 t; cvta.to.shared.u64 t, %1; cvt.u32.u64 %0, t; }" : "=r"(a) : "l"(p));
    return a;
}
__device__ __forceinline__ void cp16(uint32_t dst, const void* src) {
    asm volatile("cp.async.cg.shared.global [%0], [%1], 16;" :: "r"(dst), "l"(src) : "memory");
}
__device__ __forceinline__ void cp_commit() {
    asm volatile("cp.async.commit_group;" ::: "memory");
}
__device__ __forceinline__ void cp_wait1() {
    asm volatile("cp.async.wait_group 1;" ::: "memory");
}
__device__ __forceinline__ void ldsm4(uint32_t* r, uint32_t addr) {
    asm volatile("ldmatrix.sync.aligned.m8n8.x4.shared.b16 {%0,%1,%2,%3}, [%4];"
                 : "=r"(r[0]), "=r"(r[1]), "=r"(r[2]), "=r"(r[3]) : "r"(addr));
}
__device__ __forceinline__ void mma16816(float* d, const uint32_t* a, const uint32_t* b) {
    asm volatile("mma.sync.aligned.m16n8k16.row.col.f32.f16.f16.f32 "
                 "{%0,%1,%2,%3}, {%4,%5,%6,%7}, {%8,%9}, {%0,%1,%2,%3};"
                 : "+f"(d[0]), "+f"(d[1]), "+f"(d[2]), "+f"(d[3])
                 : "r"(a[0]), "r"(a[1]), "r"(a[2]), "r"(a[3]), "r"(b[0]), "r"(b[1]));
}

// ---------------- dtype detection (int64 vs int32 for indices) ----------------
__global__ void detect_kernel(const int* eidx, const int* etyp) {
    if (threadIdx.x == 0 && blockIdx.x == 0) {
        int ok_i = 1, ok_t = 1;
        for (int k = 0; k < 16; k++) {
            if (eidx[2 * k + 1] != 0) ok_i = 0;
            if (etyp[2 * k + 1] != 0) ok_t = 0;
        }
        g_is64_idx = ok_i;
        g_is64_typ = ok_t;
    }
}
__device__ __forceinline__ int ld_idx(const void* p, int i, int is64) {
    return is64 ? (int)((const long long*)p)[i] : ((const int*)p)[i];
}

// ---------------- prep: convert x -> fp16 with zero padding (float4 -> half4) ----------------
__global__ void conv_kernel(const float* __restrict__ src) {
    size_t q = (size_t)blockIdx.x * blockDim.x + threadIdx.x;   // quad index
    if (q >= (size_t)MPAD * DIM / 4) return;
    uint2 outv;
    if (q < (size_t)NN * DIM / 4) {
        float4 v = reinterpret_cast<const float4*>(src)[q];
        __half2 lo = __floats2half2_rn(v.x, v.y);
        __half2 hi = __floats2half2_rn(v.z, v.w);
        outv = make_uint2(*reinterpret_cast<uint32_t*>(&lo), *reinterpret_cast<uint32_t*>(&hi));
    } else {
        outv = make_uint2(0u, 0u);
    }
    reinterpret_cast<uint2*>(g_ah)[q] = outv;
}

// ---------------- prep: transpose W[r,k,n] -> Bt[r,n,k] fp16 ----------------
__global__ void prep_w_kernel(const float* __restrict__ W0, const float* __restrict__ W1) {
    int idx = blockIdx.x * blockDim.x + threadIdx.x;
    if (idx >= NR * DIM * DIM) return;
    int r = idx >> 16, n = (idx >> 8) & 255, k = idx & 255;
    size_t s = ((size_t)r << 16) + (size_t)k * DIM + n;
    g_bt0[idx] = __float2half_rn(W0[s]);
    g_bt1[idx] = __float2half_rn(W1[s]);
}

// ---------------- CSR build ----------------
__global__ void zero_cnt_kernel() {
    int i = blockIdx.x * blockDim.x + threadIdx.x;
    if (i <= NN) g_cnt[i] = 0;
}
__global__ void hist_kernel(const void* eidx) {
    int e = blockIdx.x * blockDim.x + threadIdx.x;
    if (e >= NE) return;
    int dst = ld_idx(eidx, NE + e, g_is64_idx);
    atomicAdd(&g_cnt[dst], 1);
}
__global__ void scan_kernel() {
    __shared__ int part[1024];
    const int t = threadIdx.x;
    const int PER = (NN + 1023) / 1024;   // 49
    const int base = t * PER;
    int sum = 0;
    for (int i = 0; i < PER; i++) {
        int idx = base + i;
        if (idx < NN) sum += g_cnt[idx];
    }
    part[t] = sum;
    __syncthreads();
    int acc = sum;
    for (int o = 1; o < 1024; o <<= 1) {
        int add = (t >= o) ? part[t - o] : 0;
        __syncthreads();
        acc += add;
        part[t] = acc;
        __syncthreads();
    }
    int run = acc - sum;   // exclusive prefix of this thread's chunk
    for (int i = 0; i < PER; i++) {
        int idx = base + i;
        if (idx > NN) break;
        if (idx == NN) { g_off[NN] = run; break; }
        g_off[idx] = run;
        g_cur[idx] = run;
        run += g_cnt[idx];
    }
}
__global__ void fill_kernel(const void* eidx, const void* etyp) {
    int e = blockIdx.x * blockDim.x + threadIdx.x;
    if (e >= NE) return;
    int is64i = g_is64_idx;
    int src = ld_idx(eidx, e, is64i);
    int dst = ld_idx(eidx, NE + e, is64i);
    int rel = ld_idx(etyp, e, g_is64_typ);
    int pos = atomicAdd(&g_cur[dst], 1);
    g_pack[pos] = (unsigned)src | ((unsigned)rel << 16);
}

// ---------------- GEMM: XT[r] = A @ W[r]  (mma.sync fp16 single-term) ----------------
// grid (MTILES, 2, NR), 256 threads = 8 warps in 4(m) x 2(n). CTA tile 128x128, K=256.
__global__ __launch_bounds__(256, 2) void gemm_kernel(int layer) {
    extern __shared__ char dyn[];
    const int tid  = threadIdx.x;
    const int lane = tid & 31, warp = tid >> 5;
    const int wm = warp >> 1, wn = warp & 1;
    const int mbase = blockIdx.x * 128;
    const int nbase = blockIdx.y * 128;
    const int rel   = blockIdx.z;

    const __half* Bp = (layer ? g_bt1 : g_bt0) + ((size_t)rel << 16) + (size_t)nbase * DIM;
    const __half* Ap = g_ah + (size_t)mbase * DIM;

    const uint32_t sbase = smem_u32(dyn);

    float acc[2][8][4];
    #pragma unroll
    for (int i = 0; i < 2; i++)
        #pragma unroll
        for (int j = 0; j < 8; j++)
            #pragma unroll
            for (int q = 0; q < 4; q++) acc[i][j][q] = 0.f;

    // stage loader: A | B, 128 rows x 32 fp16 each, 16B chunks
    auto load_stage = [&](int buf, int k0) {
        uint32_t sb = sbase + buf * STAGE_BYTES;
        const __half* srcs[2] = { Ap, Bp };
        #pragma unroll
        for (int arr = 0; arr < 2; arr++) {
            #pragma unroll
            for (int half = 0; half < 2; half++) {
                int rem = tid + half * 256;      // 0..511
                int row = rem >> 2, seg = rem & 3;
                cp16(sb + arr * AREA + row * ROWPITCH + seg * 16,
                     srcs[arr] + (size_t)row * DIM + k0 + seg * 8);
            }
        }
    };

    load_stage(0, 0);  cp_commit();
    load_stage(1, BK); cp_commit();

    for (int s = 0; s < 8; s++) {
        cp_wait1();
        __syncthreads();
        if (s + 2 < 8) load_stage((s + 2) % STAGES, (s + 2) * BK);
        cp_commit();

        uint32_t sb = sbase + (s % STAGES) * STAGE_BYTES;
        #pragma unroll
        for (int k16 = 0; k16 < 2; k16++) {
            uint32_t af[2][4];
            uint32_t bf[8][2];
            #pragma unroll
            for (int mt = 0; mt < 2; mt++) {
                int m_local = wm * 32 + mt * 16 + (lane & 15);
                ldsm4(af[mt], sb + m_local * ROWPITCH + k16 * 32 + (lane >> 4) * 16);
            }
            {
                uint32_t bbase = sb + AREA;
                #pragma unroll
                for (int np = 0; np < 4; np++) {
                    int n_local = wn * 64 + np * 16 + ((lane >> 4) << 3) + (lane & 7);
                    int khalf = (lane >> 3) & 1;
                    ldsm4(&bf[np * 2][0], bbase + n_local * ROWPITCH + k16 * 32 + khalf * 16);
                }
            }
            #pragma unroll
            for (int mt = 0; mt < 2; mt++)
                #pragma unroll
                for (int nt = 0; nt < 8; nt++)
                    mma16816(acc[mt][nt], af[mt], bf[nt]);
        }
    }

    // epilogue: write fp16 tile to g_xt[rel]
    #pragma unroll
    for (int mt = 0; mt < 2; mt++) {
        int gm = mbase + wm * 32 + mt * 16 + (lane >> 2);
        __half* rowp = g_xt + ((size_t)rel * MPAD + gm) * DIM + nbase + wn * 64 + 2 * (lane & 3);
        #pragma unroll
        for (int nt = 0; nt < 8; nt++) {
            __half2 lo = __floats2half2_rn(acc[mt][nt][0], acc[mt][nt][1]);
            __half2 hi = __floats2half2_rn(acc[mt][nt][2], acc[mt][nt][3]);
            *reinterpret_cast<__half2*>(rowp + nt * 8) = lo;
            *reinterpret_cast<__half2*>(rowp + 8 * DIM + nt * 8) = hi;
        }
    }
}

// ---------------- edge aggregation: out[dst] = sum relu(XT[rel,src] + b) ----------------
// warp per dst; lane covers 8 cols (16B fp16). fp32 accumulate.
// out_fp32 == nullptr -> write fp16 into g_ah (next layer's GEMM input).
__global__ __launch_bounds__(256) void edge_kernel(const float* __restrict__ bias,
                                                   float* __restrict__ out_fp32) {
    int warp = threadIdx.x >> 5, lane = threadIdx.x & 31;
    int dst = blockIdx.x * 8 + warp;
    if (dst >= NN) return;

    float b[8], acc[8];
    {
        float4 b0 = reinterpret_cast<const float4*>(bias)[lane * 2];
        float4 b1 = reinterpret_cast<const float4*>(bias)[lane * 2 + 1];
        b[0] = b0.x; b[1] = b0.y; b[2] = b0.z; b[3] = b0.w;
        b[4] = b1.x; b[5] = b1.y; b[6] = b1.z; b[7] = b1.w;
    }
    #pragma unroll
    for (int j = 0; j < 8; j++) acc[j] = 0.f;

    int s = g_off[dst], e = g_off[dst + 1];
    const uint4* xt = reinterpret_cast<const uint4*>(g_xt);   // 8 halves per uint4; row = 32 uint4

    auto addv = [&](uint4 v) {
        const __half2* hp = reinterpret_cast<const __half2*>(&v);
        #pragma unroll
        for (int j = 0; j < 4; j++) {
            float2 f = __half22float2(hp[j]);
            acc[2 * j]     += fmaxf(f.x + b[2 * j], 0.f);
            acc[2 * j + 1] += fmaxf(f.y + b[2 * j + 1], 0.f);
        }
    };

    int i = s;
    for (; i + 3 < e; i += 4) {
        unsigned p0 = __ldg(&g_pack[i]);
        unsigned p1 = __ldg(&g_pack[i + 1]);
        unsigned p2 = __ldg(&g_pack[i + 2]);
        unsigned p3 = __ldg(&g_pack[i + 3]);
        uint4 v0 = __ldg(&xt[((size_t)(p0 >> 16) * MPAD + (p0 & 0xFFFFu)) * 32 + lane]);
        uint4 v1 = __ldg(&xt[((size_t)(p1 >> 16) * MPAD + (p1 & 0xFFFFu)) * 32 + lane]);
        uint4 v2 = __ldg(&xt[((size_t)(p2 >> 16) * MPAD + (p2 & 0xFFFFu)) * 32 + lane]);
        uint4 v3 = __ldg(&xt[((size_t)(p3 >> 16) * MPAD + (p3 & 0xFFFFu)) * 32 + lane]);
        addv(v0); addv(v1); addv(v2); addv(v3);
    }
    for (; i < e; i++) {
        unsigned p0 = __ldg(&g_pack[i]);
        addv(__ldg(&xt[((size_t)(p0 >> 16) * MPAD + (p0 & 0xFFFFu)) * 32 + lane]));
    }

    if (out_fp32) {
        float4* op = reinterpret_cast<float4*>(out_fp32) + (size_t)dst * 64 + lane * 2;
        op[0] = make_float4(acc[0], acc[1], acc[2], acc[3]);
        op[1] = make_float4(acc[4], acc[5], acc[6], acc[7]);
    } else {
        uint4 ov;
        __half2 h0 = __floats2half2_rn(acc[0], acc[1]);
        __half2 h1 = __floats2half2_rn(acc[2], acc[3]);
        __half2 h2 = __floats2half2_rn(acc[4], acc[5]);
        __half2 h3 = __floats2half2_rn(acc[6], acc[7]);
        ov.x = *reinterpret_cast<uint32_t*>(&h0);
        ov.y = *reinterpret_cast<uint32_t*>(&h1);
        ov.z = *reinterpret_cast<uint32_t*>(&h2);
        ov.w = *reinterpret_cast<uint32_t*>(&h3);
        reinterpret_cast<uint4*>(g_ah)[(size_t)dst * 32 + lane] = ov;
    }
}

// ---------------- launch ----------------
extern "C" void kernel_launch(void* const* d_in, const int* in_sizes, int n_in,
                              void* d_out, int out_size) {
    const float* x  = (const float*)d_in[0];
    const float* W0 = (const float*)d_in[1];
    const float* b0 = (const float*)d_in[2];
    const float* W1 = (const float*)d_in[3];
    const float* b1 = (const float*)d_in[4];
    const void*  ei = d_in[5];
    const void*  et = d_in[6];
    float* out = (float*)d_out;

    cudaFuncSetAttribute(gemm_kernel, cudaFuncAttributeMaxDynamicSharedMemorySize, GEMM_SMEM);

    int conv_blocks = (MPAD * DIM / 4 + 255) / 256;

    // Order chosen so the layer-0 GEMM sits in the ncu -s 5 -c 1 window
    detect_kernel<<<1, 32>>>((const int*)ei, (const int*)et);            // 1
    conv_kernel<<<conv_blocks, 256>>>(x);                                // 2
    prep_w_kernel<<<(NR * DIM * DIM + 255) / 256, 256>>>(W0, W1);        // 3
    gemm_kernel<<<dim3(MTILES, 2, NR), 256, GEMM_SMEM>>>(0);             // 4  <- profiled
    zero_cnt_kernel<<<(NN + 256) / 256, 256>>>();                        // 5
    hist_kernel<<<(NE + 255) / 256, 256>>>(ei);                          // 6
    scan_kernel<<<1, 1024>>>();                                          // 7
    fill_kernel<<<(NE + 255) / 256, 256>>>(ei, et);                      // 8

    edge_kernel<<<(NN + 7) / 8, 256>>>(b0, nullptr);                     // -> g_ah (fp16 h)

    // layer 2
    gemm_kernel<<<dim3(MTILES, 2, NR), 256, GEMM_SMEM>>>(1);
    edge_kernel<<<(NN + 7) / 8, 256>>>(b1, out);
}

// round 11
// speedup vs baseline: 2.4989x; 1.0795x over previous
#include <cuda_runtime.h>
#include <cuda_fp16.h>
#include <cstdint>

#define NN   50000
#define NE   800000
#define NR   8
#define DIM  256
#define MPAD 50048          // 391 * 128
#define MTILES 391

// GEMM tiling
#define BK        64
#define STAGES    3
#define AREA      (128 * 128)        // 16384 B: 128 rows x 64 fp16, XOR-swizzled
#define STAGE_BYTES (2 * AREA)       // A, B
#define GEMM_SMEM (STAGES * STAGE_BYTES)   // 98304

// ---------------- scratch (__device__ globals; no allocation allowed) ----------------
__device__ __align__(256) __half  g_xt[NR * MPAD * DIM];     // 205 MB
__device__ __align__(256) __half  g_ah[MPAD * DIM];          // GEMM A input (x, then h)
__device__ __align__(256) __half  g_bt0[NR * DIM * DIM];
__device__ __align__(256) __half  g_bt1[NR * DIM * DIM];
__device__ int       g_cnt[NN + 1];
__device__ int       g_off[NN + 1];
__device__ int       g_cur[NN];
__device__ unsigned  g_pack[NE];
__device__ int       g_is64_idx;
__device__ int       g_is64_typ;

// ---------------- PTX helpers (base-target only) ----------------
__device__ __forceinline__ uint32_t smem_u32(const void* p) {
    uint32_t a;
    asm("{ .reg .u64 t; cvta.to.shared.u64 t, %1; cvt.u32.u64 %0, t; }" : "=r"(a) : "l"(p));
    return a;
}
__device__ __forceinline__ void cp16(uint32_t dst, const void* src) {
    asm volatile("cp.async.cg.shared.global [%0], [%1], 16;" :: "r"(dst), "l"(src) : "memory");
}
__device__ __forceinline__ void cp_commit() {
    asm volatile("cp.async.commit_group;" ::: "memory");
}
__device__ __forceinline__ void cp_wait1() {
    asm volatile("cp.async.wait_group 1;" ::: "memory");
}
__device__ __forceinline__ void ldsm4(uint32_t* r, uint32_t addr) {
    asm volatile("ldmatrix.sync.aligned.m8n8.x4.shared.b16 {%0,%1,%2,%3}, [%4];"
                 : "=r"(r[0]), "=r"(r[1]), "=r"(r[2]), "=r"(r[3]) : "r"(addr));
}
__device__ __forceinline__ void mma16816(float* d, const uint32_t* a, const uint32_t* b) {
    asm volatile("mma.sync.aligned.m16n8k16.row.col.f32.f16.f16.f32 "
                 "{%0,%1,%2,%3}, {%4,%5,%6,%7}, {%8,%9}, {%0,%1,%2,%3};"
                 : "+f"(d[0]), "+f"(d[1]), "+f"(d[2]), "+f"(d[3])
                 : "r"(a[0]), "r"(a[1]), "r"(a[2]), "r"(a[3]), "r"(b[0]), "r"(b[1]));
}

// ---------------- dtype detection (int64 vs int32 for indices) ----------------
__global__ void detect_kernel(const int* eidx, const int* etyp) {
    if (threadIdx.x == 0 && blockIdx.x == 0) {
        int ok_i = 1, ok_t = 1;
        for (int k = 0; k < 16; k++) {
            if (eidx[2 * k + 1] != 0) ok_i = 0;
            if (etyp[2 * k + 1] != 0) ok_t = 0;
        }
        g_is64_idx = ok_i;
        g_is64_typ = ok_t;
    }
}
__device__ __forceinline__ int ld_idx(const void* p, int i, int is64) {
    return is64 ? (int)((const long long*)p)[i] : ((const int*)p)[i];
}

// ---------------- prep: convert x -> fp16 with zero padding (float4 -> half4) ----------------
__global__ void conv_kernel(const float* __restrict__ src) {
    size_t q = (size_t)blockIdx.x * blockDim.x + threadIdx.x;   // quad index
    if (q >= (size_t)MPAD * DIM / 4) return;
    uint2 outv;
    if (q < (size_t)NN * DIM / 4) {
        float4 v = reinterpret_cast<const float4*>(src)[q];
        __half2 lo = __floats2half2_rn(v.x, v.y);
        __half2 hi = __floats2half2_rn(v.z, v.w);
        outv = make_uint2(*reinterpret_cast<uint32_t*>(&lo), *reinterpret_cast<uint32_t*>(&hi));
    } else {
        outv = make_uint2(0u, 0u);
    }
    reinterpret_cast<uint2*>(g_ah)[q] = outv;
}

// ---------------- prep: transpose W[r,k,n] -> Bt[r,n,k] fp16 ----------------
__global__ void prep_w_kernel(const float* __restrict__ W0, const float* __restrict__ W1) {
    int idx = blockIdx.x * blockDim.x + threadIdx.x;
    if (idx >= NR * DIM * DIM) return;
    int r = idx >> 16, n = (idx >> 8) & 255, k = idx & 255;
    size_t s = ((size_t)r << 16) + (size_t)k * DIM + n;
    g_bt0[idx] = __float2half_rn(W0[s]);
    g_bt1[idx] = __float2half_rn(W1[s]);
}

// ---------------- CSR build ----------------
__global__ void zero_cnt_kernel() {
    int i = blockIdx.x * blockDim.x + threadIdx.x;
    if (i <= NN) g_cnt[i] = 0;
}
__global__ void hist_kernel(const void* eidx) {
    int e = blockIdx.x * blockDim.x + threadIdx.x;
    if (e >= NE) return;
    int dst = ld_idx(eidx, NE + e, g_is64_idx);
    atomicAdd(&g_cnt[dst], 1);
}
__global__ void scan_kernel() {
    __shared__ int part[1024];
    const int t = threadIdx.x;
    const int PER = (NN + 1023) / 1024;   // 49
    const int base = t * PER;
    int sum = 0;
    for (int i = 0; i < PER; i++) {
        int idx = base + i;
        if (idx < NN) sum += g_cnt[idx];
    }
    part[t] = sum;
    __syncthreads();
    int acc = sum;
    for (int o = 1; o < 1024; o <<= 1) {
        int add = (t >= o) ? part[t - o] : 0;
        __syncthreads();
        acc += add;
        part[t] = acc;
        __syncthreads();
    }
    int run = acc - sum;   // exclusive prefix of this thread's chunk
    for (int i = 0; i < PER; i++) {
        int idx = base + i;
        if (idx > NN) break;
        if (idx == NN) { g_off[NN] = run; break; }
        g_off[idx] = run;
        g_cur[idx] = run;
        run += g_cnt[idx];
    }
}
__global__ void fill_kernel(const void* eidx, const void* etyp) {
    int e = blockIdx.x * blockDim.x + threadIdx.x;
    if (e >= NE) return;
    int is64i = g_is64_idx;
    int src = ld_idx(eidx, e, is64i);
    int dst = ld_idx(eidx, NE + e, is64i);
    int rel = ld_idx(etyp, e, g_is64_typ);
    int pos = atomicAdd(&g_cur[dst], 1);
    g_pack[pos] = (unsigned)src | ((unsigned)rel << 16);
}

// ---------------- GEMM: XT[r] = A @ W[r]  (mma.sync fp16, BK=64, XOR swizzle) ----------------
// grid (MTILES, 2, NR), 256 threads = 8 warps in 4(m) x 2(n). CTA tile 128x128, K=256.
__global__ __launch_bounds__(256, 2) void gemm_kernel(int layer) {
    extern __shared__ char dyn[];
    const int tid  = threadIdx.x;
    const int lane = tid & 31, warp = tid >> 5;
    const int wm = warp >> 1, wn = warp & 1;
    const int mbase = blockIdx.x * 128;
    const int nbase = blockIdx.y * 128;
    const int rel   = blockIdx.z;

    const __half* Bp = (layer ? g_bt1 : g_bt0) + ((size_t)rel << 16) + (size_t)nbase * DIM;
    const __half* Ap = g_ah + (size_t)mbase * DIM;

    const uint32_t sbase = smem_u32(dyn);

    float acc[2][8][4];
    #pragma unroll
    for (int i = 0; i < 2; i++)
        #pragma unroll
        for (int j = 0; j < 8; j++)
            #pragma unroll
            for (int q = 0; q < 4; q++) acc[i][j][q] = 0.f;

    // stage loader: A | B, 128 rows x 64 fp16 each (128 B/row), XOR swizzle on 16B segs
    auto load_stage = [&](int buf, int k0) {
        uint32_t sb = sbase + buf * STAGE_BYTES;
        const __half* srcs[2] = { Ap, Bp };
        #pragma unroll
        for (int arr = 0; arr < 2; arr++) {
            #pragma unroll
            for (int it = 0; it < 4; it++) {
                int rem = tid + it * 256;        // 0..1023
                int row = rem >> 3, seg = rem & 7;
                cp16(sb + arr * AREA + row * 128 + ((seg ^ (row & 7)) << 4),
                     srcs[arr] + (size_t)row * DIM + k0 + seg * 8);
            }
        }
    };

    load_stage(0, 0);  cp_commit();
    load_stage(1, BK); cp_commit();

    #pragma unroll
    for (int s = 0; s < 4; s++) {
        cp_wait1();
        __syncthreads();
        if (s + 2 < 4) load_stage((s + 2) % STAGES, (s + 2) * BK);
        cp_commit();

        uint32_t sb = sbase + (s % STAGES) * STAGE_BYTES;
        #pragma unroll
        for (int k16 = 0; k16 < 4; k16++) {
            uint32_t af[2][4];
            uint32_t bf[8][2];
            #pragma unroll
            for (int mt = 0; mt < 2; mt++) {
                int m_local = wm * 32 + mt * 16 + (lane & 15);
                int seg = k16 * 2 + (lane >> 4);
                ldsm4(af[mt], sb + m_local * 128 + ((seg ^ (m_local & 7)) << 4));
            }
            {
                uint32_t bbase = sb + AREA;
                #pragma unroll
                for (int np = 0; np < 4; np++) {
                    int n_local = wn * 64 + np * 16 + ((lane >> 4) << 3) + (lane & 7);
                    int seg = k16 * 2 + ((lane >> 3) & 1);
                    ldsm4(&bf[np * 2][0], bbase + n_local * 128 + ((seg ^ (n_local & 7)) << 4));
                }
            }
            #pragma unroll
            for (int mt = 0; mt < 2; mt++)
                #pragma unroll
                for (int nt = 0; nt < 8; nt++)
                    mma16816(acc[mt][nt], af[mt], bf[nt]);
        }
    }

    // epilogue: write fp16 tile to g_xt[rel]
    #pragma unroll
    for (int mt = 0; mt < 2; mt++) {
        int gm = mbase + wm * 32 + mt * 16 + (lane >> 2);
        __half* rowp = g_xt + ((size_t)rel * MPAD + gm) * DIM + nbase + wn * 64 + 2 * (lane & 3);
        #pragma unroll
        for (int nt = 0; nt < 8; nt++) {
            __half2 lo = __floats2half2_rn(acc[mt][nt][0], acc[mt][nt][1]);
            __half2 hi = __floats2half2_rn(acc[mt][nt][2], acc[mt][nt][3]);
            *reinterpret_cast<__half2*>(rowp + nt * 8) = lo;
            *reinterpret_cast<__half2*>(rowp + 8 * DIM + nt * 8) = hi;
        }
    }
}

// ---------------- edge aggregation: out[dst] = sum relu(XT[rel,src] + b) ----------------
// warp per dst; lane covers 8 cols (16B fp16). fp32 accumulate.
// out_fp32 == nullptr -> write fp16 into g_ah (next layer's GEMM input).
__global__ __launch_bounds__(256) void edge_kernel(const float* __restrict__ bias,
                                                   float* __restrict__ out_fp32) {
    int warp = threadIdx.x >> 5, lane = threadIdx.x & 31;
    int dst = blockIdx.x * 8 + warp;
    if (dst >= NN) return;

    float b[8], acc[8];
    {
        float4 b0 = reinterpret_cast<const float4*>(bias)[lane * 2];
        float4 b1 = reinterpret_cast<const float4*>(bias)[lane * 2 + 1];
        b[0] = b0.x; b[1] = b0.y; b[2] = b0.z; b[3] = b0.w;
        b[4] = b1.x; b[5] = b1.y; b[6] = b1.z; b[7] = b1.w;
    }
    #pragma unroll
    for (int j = 0; j < 8; j++) acc[j] = 0.f;

    int s = g_off[dst], e = g_off[dst + 1];
    const uint4* xt = reinterpret_cast<const uint4*>(g_xt);   // 8 halves per uint4; row = 32 uint4

    auto addv = [&](uint4 v) {
        const __half2* hp = reinterpret_cast<const __half2*>(&v);
        #pragma unroll
        for (int j = 0; j < 4; j++) {
            float2 f = __half22float2(hp[j]);
            acc[2 * j]     += fmaxf(f.x + b[2 * j], 0.f);
            acc[2 * j + 1] += fmaxf(f.y + b[2 * j + 1], 0.f);
        }
    };

    int i = s;
    for (; i + 3 < e; i += 4) {
        unsigned p0 = __ldg(&g_pack[i]);
        unsigned p1 = __ldg(&g_pack[i + 1]);
        unsigned p2 = __ldg(&g_pack[i + 2]);
        unsigned p3 = __ldg(&g_pack[i + 3]);
        uint4 v0 = __ldg(&xt[((size_t)(p0 >> 16) * MPAD + (p0 & 0xFFFFu)) * 32 + lane]);
        uint4 v1 = __ldg(&xt[((size_t)(p1 >> 16) * MPAD + (p1 & 0xFFFFu)) * 32 + lane]);
        uint4 v2 = __ldg(&xt[((size_t)(p2 >> 16) * MPAD + (p2 & 0xFFFFu)) * 32 + lane]);
        uint4 v3 = __ldg(&xt[((size_t)(p3 >> 16) * MPAD + (p3 & 0xFFFFu)) * 32 + lane]);
        addv(v0); addv(v1); addv(v2); addv(v3);
    }
    for (; i < e; i++) {
        unsigned p0 = __ldg(&g_pack[i]);
        addv(__ldg(&xt[((size_t)(p0 >> 16) * MPAD + (p0 & 0xFFFFu)) * 32 + lane]));
    }

    if (out_fp32) {
        float4* op = reinterpret_cast<float4*>(out_fp32) + (size_t)dst * 64 + lane * 2;
        op[0] = make_float4(acc[0], acc[1], acc[2], acc[3]);
        op[1] = make_float4(acc[4], acc[5], acc[6], acc[7]);
    } else {
        uint4 ov;
        __half2 h0 = __floats2half2_rn(acc[0], acc[1]);
        __half2 h1 = __floats2half2_rn(acc[2], acc[3]);
        __half2 h2 = __floats2half2_rn(acc[4], acc[5]);
        __half2 h3 = __floats2half2_rn(acc[6], acc[7]);
        ov.x = *reinterpret_cast<uint32_t*>(&h0);
        ov.y = *reinterpret_cast<uint32_t*>(&h1);
        ov.z = *reinterpret_cast<uint32_t*>(&h2);
        ov.w = *reinterpret_cast<uint32_t*>(&h3);
        reinterpret_cast<uint4*>(g_ah)[(size_t)dst * 32 + lane] = ov;
    }
}

// ---------------- launch ----------------
extern "C" void kernel_launch(void* const* d_in, const int* in_sizes, int n_in,
                              void* d_out, int out_size) {
    const float* x  = (const float*)d_in[0];
    const float* W0 = (const float*)d_in[1];
    const float* b0 = (const float*)d_in[2];
    const float* W1 = (const float*)d_in[3];
    const float* b1 = (const float*)d_in[4];
    const void*  ei = d_in[5];
    const void*  et = d_in[6];
    float* out = (float*)d_out;

    cudaFuncSetAttribute(gemm_kernel, cudaFuncAttributeMaxDynamicSharedMemorySize, GEMM_SMEM);

    int conv_blocks = (MPAD * DIM / 4 + 255) / 256;

    // Order chosen so the layer-0 GEMM sits in the ncu profiling window (4th launch)
    detect_kernel<<<1, 32>>>((const int*)ei, (const int*)et);            // 1
    conv_kernel<<<conv_blocks, 256>>>(x);                                // 2
    prep_w_kernel<<<(NR * DIM * DIM + 255) / 256, 256>>>(W0, W1);        // 3
    gemm_kernel<<<dim3(MTILES, 2, NR), 256, GEMM_SMEM>>>(0);             // 4  <- profiled
    zero_cnt_kernel<<<(NN + 256) / 256, 256>>>();                        // 5
    hist_kernel<<<(NE + 255) / 256, 256>>>(ei);                          // 6
    scan_kernel<<<1, 1024>>>();                                          // 7
    fill_kernel<<<(NE + 255) / 256, 256>>>(ei, et);                      // 8

    edge_kernel<<<(NN + 7) / 8, 256>>>(b0, nullptr);                     // -> g_ah (fp16 h)

    // layer 2
    gemm_kernel<<<dim3(MTILES, 2, NR), 256, GEMM_SMEM>>>(1);
    edge_kernel<<<(NN + 7) / 8, 256>>>(b1, out);
}

// round 12
// speedup vs baseline: 2.6101x; 1.0445x over previous
#include <cuda_runtime.h>
#include <cuda_fp16.h>
#include <cstdint>

#define NN   50000
#define NE   800000
#define NR   8
#define DIM  256
#define MPAD 50048          // 391 * 128
#define MTILES 391

// GEMM tiling: CTA 128x128xK256, BK=64, 4 warps of 64x64
#define BK        64
#define STAGES    3
#define AREA      (128 * 128)        // 16384 B: 128 rows x 64 fp16, XOR-swizzled
#define STAGE_BYTES (2 * AREA)       // A, B
#define GEMM_SMEM (STAGES * STAGE_BYTES)   // 98304

// ---------------- scratch (__device__ globals; no allocation allowed) ----------------
__device__ __align__(256) __half  g_xt[NR * MPAD * DIM];     // 205 MB
__device__ __align__(256) __half  g_ah[MPAD * DIM];          // GEMM A input (x, then h)
__device__ __align__(256) __half  g_bt0[NR * DIM * DIM];
__device__ __align__(256) __half  g_bt1[NR * DIM * DIM];
__device__ int       g_cnt[NN + 1];
__device__ int       g_off[NN + 1];
__device__ int       g_cur[NN];
__device__ unsigned  g_pack[NE];
__device__ int       g_is64_idx;
__device__ int       g_is64_typ;

// ---------------- PTX helpers (base-target only) ----------------
__device__ __forceinline__ uint32_t smem_u32(const void* p) {
    uint32_t a;
    asm("{ .reg .u64 t; cvta.to.shared.u64 t, %1; cvt.u32.u64 %0, t; }" : "=r"(a) : "l"(p));
    return a;
}
__device__ __forceinline__ void cp16(uint32_t dst, const void* src) {
    asm volatile("cp.async.cg.shared.global [%0], [%1], 16;" :: "r"(dst), "l"(src) : "memory");
}
__device__ __forceinline__ void cp_commit() {
    asm volatile("cp.async.commit_group;" ::: "memory");
}
__device__ __forceinline__ void cp_wait1() {
    asm volatile("cp.async.wait_group 1;" ::: "memory");
}
__device__ __forceinline__ void ldsm4(uint32_t* r, uint32_t addr) {
    asm volatile("ldmatrix.sync.aligned.m8n8.x4.shared.b16 {%0,%1,%2,%3}, [%4];"
                 : "=r"(r[0]), "=r"(r[1]), "=r"(r[2]), "=r"(r[3]) : "r"(addr));
}
__device__ __forceinline__ void mma16816(float* d, const uint32_t* a, const uint32_t* b) {
    asm volatile("mma.sync.aligned.m16n8k16.row.col.f32.f16.f16.f32 "
                 "{%0,%1,%2,%3}, {%4,%5,%6,%7}, {%8,%9}, {%0,%1,%2,%3};"
                 : "+f"(d[0]), "+f"(d[1]), "+f"(d[2]), "+f"(d[3])
                 : "r"(a[0]), "r"(a[1]), "r"(a[2]), "r"(a[3]), "r"(b[0]), "r"(b[1]));
}

// ---------------- dtype detection (int64 vs int32 for indices) ----------------
__global__ void detect_kernel(const int* eidx, const int* etyp) {
    if (threadIdx.x == 0 && blockIdx.x == 0) {
        int ok_i = 1, ok_t = 1;
        for (int k = 0; k < 16; k++) {
            if (eidx[2 * k + 1] != 0) ok_i = 0;
            if (etyp[2 * k + 1] != 0) ok_t = 0;
        }
        g_is64_idx = ok_i;
        g_is64_typ = ok_t;
    }
}
__device__ __forceinline__ int ld_idx(const void* p, int i, int is64) {
    return is64 ? (int)((const long long*)p)[i] : ((const int*)p)[i];
}

// ---------------- prep: convert x -> fp16 with zero padding (float4 -> half4) ----------------
__global__ void conv_kernel(const float* __restrict__ src) {
    size_t q = (size_t)blockIdx.x * blockDim.x + threadIdx.x;   // quad index
    if (q >= (size_t)MPAD * DIM / 4) return;
    uint2 outv;
    if (q < (size_t)NN * DIM / 4) {
        float4 v = reinterpret_cast<const float4*>(src)[q];
        __half2 lo = __floats2half2_rn(v.x, v.y);
        __half2 hi = __floats2half2_rn(v.z, v.w);
        outv = make_uint2(*reinterpret_cast<uint32_t*>(&lo), *reinterpret_cast<uint32_t*>(&hi));
    } else {
        outv = make_uint2(0u, 0u);
    }
    reinterpret_cast<uint2*>(g_ah)[q] = outv;
}

// ---------------- prep: transpose W[r,k,n] -> Bt[r,n,k] fp16 ----------------
__global__ void prep_w_kernel(const float* __restrict__ W0, const float* __restrict__ W1) {
    int idx = blockIdx.x * blockDim.x + threadIdx.x;
    if (idx >= NR * DIM * DIM) return;
    int r = idx >> 16, n = (idx >> 8) & 255, k = idx & 255;
    size_t s = ((size_t)r << 16) + (size_t)k * DIM + n;
    g_bt0[idx] = __float2half_rn(W0[s]);
    g_bt1[idx] = __float2half_rn(W1[s]);
}

// ---------------- CSR build ----------------
__global__ void zero_cnt_kernel() {
    int i = blockIdx.x * blockDim.x + threadIdx.x;
    if (i <= NN) g_cnt[i] = 0;
}
__global__ void hist_kernel(const void* eidx) {
    int e = blockIdx.x * blockDim.x + threadIdx.x;
    if (e >= NE) return;
    int dst = ld_idx(eidx, NE + e, g_is64_idx);
    atomicAdd(&g_cnt[dst], 1);
}
__global__ void scan_kernel() {
    __shared__ int part[1024];
    const int t = threadIdx.x;
    const int PER = (NN + 1023) / 1024;   // 49
    const int base = t * PER;
    int sum = 0;
    for (int i = 0; i < PER; i++) {
        int idx = base + i;
        if (idx < NN) sum += g_cnt[idx];
    }
    part[t] = sum;
    __syncthreads();
    int acc = sum;
    for (int o = 1; o < 1024; o <<= 1) {
        int add = (t >= o) ? part[t - o] : 0;
        __syncthreads();
        acc += add;
        part[t] = acc;
        __syncthreads();
    }
    int run = acc - sum;   // exclusive prefix of this thread's chunk
    for (int i = 0; i < PER; i++) {
        int idx = base + i;
        if (idx > NN) break;
        if (idx == NN) { g_off[NN] = run; break; }
        g_off[idx] = run;
        g_cur[idx] = run;
        run += g_cnt[idx];
    }
}
__global__ void fill_kernel(const void* eidx, const void* etyp) {
    int e = blockIdx.x * blockDim.x + threadIdx.x;
    if (e >= NE) return;
    int is64i = g_is64_idx;
    int src = ld_idx(eidx, e, is64i);
    int dst = ld_idx(eidx, NE + e, is64i);
    int rel = ld_idx(etyp, e, g_is64_typ);
    int pos = atomicAdd(&g_cur[dst], 1);
    g_pack[pos] = (unsigned)src | ((unsigned)rel << 16);
}

// ---------------- GEMM: XT[r] = A @ W[r]  (mma.sync fp16, 4 warps of 64x64) ----------------
// grid (MTILES, 2, NR), 128 threads = 4 warps in 2(m) x 2(n). CTA tile 128x128, K=256.
__global__ __launch_bounds__(128, 2) void gemm_kernel(int layer) {
    extern __shared__ char dyn[];
    const int tid  = threadIdx.x;
    const int lane = tid & 31, warp = tid >> 5;
    const int wm = warp >> 1, wn = warp & 1;
    const int mbase = blockIdx.x * 128;
    const int nbase = blockIdx.y * 128;
    const int rel   = blockIdx.z;

    const __half* Bp = (layer ? g_bt1 : g_bt0) + ((size_t)rel << 16) + (size_t)nbase * DIM;
    const __half* Ap = g_ah + (size_t)mbase * DIM;

    const uint32_t sbase = smem_u32(dyn);

    float acc[4][8][4];
    #pragma unroll
    for (int i = 0; i < 4; i++)
        #pragma unroll
        for (int j = 0; j < 8; j++)
            #pragma unroll
            for (int q = 0; q < 4; q++) acc[i][j][q] = 0.f;

    // stage loader: A | B, 128 rows x 64 fp16 each (128 B/row), XOR swizzle on 16B segs
    auto load_stage = [&](int buf, int k0) {
        uint32_t sb = sbase + buf * STAGE_BYTES;
        const __half* srcs[2] = { Ap, Bp };
        #pragma unroll
        for (int arr = 0; arr < 2; arr++) {
            #pragma unroll
            for (int it = 0; it < 8; it++) {
                int rem = tid + it * 128;        // 0..1023
                int row = rem >> 3, seg = rem & 7;
                cp16(sb + arr * AREA + row * 128 + ((seg ^ (row & 7)) << 4),
                     srcs[arr] + (size_t)row * DIM + k0 + seg * 8);
            }
        }
    };

    load_stage(0, 0);  cp_commit();
    load_stage(1, BK); cp_commit();

    #pragma unroll
    for (int s = 0; s < 4; s++) {
        cp_wait1();
        __syncthreads();
        if (s + 2 < 4) load_stage((s + 2) % STAGES, (s + 2) * BK);
        cp_commit();

        uint32_t sb = sbase + (s % STAGES) * STAGE_BYTES;
        #pragma unroll
        for (int k16 = 0; k16 < 4; k16++) {
            uint32_t af[4][4];
            uint32_t bf[8][2];
            #pragma unroll
            for (int mt = 0; mt < 4; mt++) {
                int m_local = wm * 64 + mt * 16 + (lane & 15);
                int seg = k16 * 2 + (lane >> 4);
                ldsm4(af[mt], sb + m_local * 128 + ((seg ^ (m_local & 7)) << 4));
            }
            {
                uint32_t bbase = sb + AREA;
                #pragma unroll
                for (int np = 0; np < 4; np++) {
                    int n_local = wn * 64 + np * 16 + ((lane >> 4) << 3) + (lane & 7);
                    int seg = k16 * 2 + ((lane >> 3) & 1);
                    ldsm4(&bf[np * 2][0], bbase + n_local * 128 + ((seg ^ (n_local & 7)) << 4));
                }
            }
            #pragma unroll
            for (int mt = 0; mt < 4; mt++)
                #pragma unroll
                for (int nt = 0; nt < 8; nt++)
                    mma16816(acc[mt][nt], af[mt], bf[nt]);
        }
    }

    // epilogue: write fp16 tile to g_xt[rel]
    #pragma unroll
    for (int mt = 0; mt < 4; mt++) {
        int gm = mbase + wm * 64 + mt * 16 + (lane >> 2);
        __half* rowp = g_xt + ((size_t)rel * MPAD + gm) * DIM + nbase + wn * 64 + 2 * (lane & 3);
        #pragma unroll
        for (int nt = 0; nt < 8; nt++) {
            __half2 lo = __floats2half2_rn(acc[mt][nt][0], acc[mt][nt][1]);
            __half2 hi = __floats2half2_rn(acc[mt][nt][2], acc[mt][nt][3]);
            *reinterpret_cast<__half2*>(rowp + nt * 8) = lo;
            *reinterpret_cast<__half2*>(rowp + 8 * DIM + nt * 8) = hi;
        }
    }
}

// ---------------- edge aggregation: out[dst] = sum relu(XT[rel,src] + b) ----------------
// warp per dst; lane covers 8 cols (16B fp16). fp32 accumulate.
// out_fp32 == nullptr -> write fp16 into g_ah (next layer's GEMM input).
__global__ __launch_bounds__(256) void edge_kernel(const float* __restrict__ bias,
                                                   float* __restrict__ out_fp32) {
    int warp = threadIdx.x >> 5, lane = threadIdx.x & 31;
    int dst = blockIdx.x * 8 + warp;
    if (dst >= NN) return;

    float b[8], acc[8];
    {
        float4 b0 = reinterpret_cast<const float4*>(bias)[lane * 2];
        float4 b1 = reinterpret_cast<const float4*>(bias)[lane * 2 + 1];
        b[0] = b0.x; b[1] = b0.y; b[2] = b0.z; b[3] = b0.w;
        b[4] = b1.x; b[5] = b1.y; b[6] = b1.z; b[7] = b1.w;
    }
    #pragma unroll
    for (int j = 0; j < 8; j++) acc[j] = 0.f;

    int s = g_off[dst], e = g_off[dst + 1];
    const uint4* xt = reinterpret_cast<const uint4*>(g_xt);   // 8 halves per uint4; row = 32 uint4

    auto addv = [&](uint4 v) {
        const __half2* hp = reinterpret_cast<const __half2*>(&v);
        #pragma unroll
        for (int j = 0; j < 4; j++) {
            float2 f = __half22float2(hp[j]);
            acc[2 * j]     += fmaxf(f.x + b[2 * j], 0.f);
            acc[2 * j + 1] += fmaxf(f.y + b[2 * j + 1], 0.f);
        }
    };

    int i = s;
    for (; i + 3 < e; i += 4) {
        unsigned p0 = __ldg(&g_pack[i]);
        unsigned p1 = __ldg(&g_pack[i + 1]);
        unsigned p2 = __ldg(&g_pack[i + 2]);
        unsigned p3 = __ldg(&g_pack[i + 3]);
        uint4 v0 = __ldg(&xt[((size_t)(p0 >> 16) * MPAD + (p0 & 0xFFFFu)) * 32 + lane]);
        uint4 v1 = __ldg(&xt[((size_t)(p1 >> 16) * MPAD + (p1 & 0xFFFFu)) * 32 + lane]);
        uint4 v2 = __ldg(&xt[((size_t)(p2 >> 16) * MPAD + (p2 & 0xFFFFu)) * 32 + lane]);
        uint4 v3 = __ldg(&xt[((size_t)(p3 >> 16) * MPAD + (p3 & 0xFFFFu)) * 32 + lane]);
        addv(v0); addv(v1); addv(v2); addv(v3);
    }
    for (; i < e; i++) {
        unsigned p0 = __ldg(&g_pack[i]);
        addv(__ldg(&xt[((size_t)(p0 >> 16) * MPAD + (p0 & 0xFFFFu)) * 32 + lane]));
    }

    if (out_fp32) {
        float4* op = reinterpret_cast<float4*>(out_fp32) + (size_t)dst * 64 + lane * 2;
        op[0] = make_float4(acc[0], acc[1], acc[2], acc[3]);
        op[1] = make_float4(acc[4], acc[5], acc[6], acc[7]);
    } else {
        uint4 ov;
        __half2 h0 = __floats2half2_rn(acc[0], acc[1]);
        __half2 h1 = __floats2half2_rn(acc[2], acc[3]);
        __half2 h2 = __floats2half2_rn(acc[4], acc[5]);
        __half2 h3 = __floats2half2_rn(acc[6], acc[7]);
        ov.x = *reinterpret_cast<uint32_t*>(&h0);
        ov.y = *reinterpret_cast<uint32_t*>(&h1);
        ov.z = *reinterpret_cast<uint32_t*>(&h2);
        ov.w = *reinterpret_cast<uint32_t*>(&h3);
        reinterpret_cast<uint4*>(g_ah)[(size_t)dst * 32 + lane] = ov;
    }
}

// ---------------- launch ----------------
extern "C" void kernel_launch(void* const* d_in, const int* in_sizes, int n_in,
                              void* d_out, int out_size) {
    const float* x  = (const float*)d_in[0];
    const float* W0 = (const float*)d_in[1];
    const float* b0 = (const float*)d_in[2];
    const float* W1 = (const float*)d_in[3];
    const float* b1 = (const float*)d_in[4];
    const void*  ei = d_in[5];
    const void*  et = d_in[6];
    float* out = (float*)d_out;

    cudaFuncSetAttribute(gemm_kernel, cudaFuncAttributeMaxDynamicSharedMemorySize, GEMM_SMEM);

    int conv_blocks = (MPAD * DIM / 4 + 255) / 256;

    // Order chosen so the layer-0 GEMM sits in the ncu profiling window (4th launch)
    detect_kernel<<<1, 32>>>((const int*)ei, (const int*)et);            // 1
    conv_kernel<<<conv_blocks, 256>>>(x);                                // 2
    prep_w_kernel<<<(NR * DIM * DIM + 255) / 256, 256>>>(W0, W1);        // 3
    gemm_kernel<<<dim3(MTILES, 2, NR), 128, GEMM_SMEM>>>(0);             // 4  <- profiled
    zero_cnt_kernel<<<(NN + 256) / 256, 256>>>();                        // 5
    hist_kernel<<<(NE + 255) / 256, 256>>>(ei);                          // 6
    scan_kernel<<<1, 1024>>>();                                          // 7
    fill_kernel<<<(NE + 255) / 256, 256>>>(ei, et);                      // 8

    edge_kernel<<<(NN + 7) / 8, 256>>>(b0, nullptr);                     // -> g_ah (fp16 h)

    // layer 2
    gemm_kernel<<<dim3(MTILES, 2, NR), 128, GEMM_SMEM>>>(1);
    edge_kernel<<<(NN + 7) / 8, 256>>>(b1, out);
}

// round 13
// speedup vs baseline: 2.7568x; 1.0562x over previous
#include <cuda_runtime.h>
#include <cuda_fp16.h>
#include <cstdint>

#define NN   50000
#define NE   800000
#define NR   8
#define DIM  256
#define MPAD 50048          // 391 * 128
#define MTILES 391

// GEMM tiling: CTA 128x128xK256, BK=64, 4 warps of 64x64
#define BK        64
#define STAGES    3
#define AREA      (128 * 128)        // 16384 B: 128 rows x 64 fp16, XOR-swizzled
#define STAGE_BYTES (2 * AREA)       // A, B
#define GEMM_SMEM (STAGES * STAGE_BYTES)   // 98304

// ---------------- scratch (__device__ globals; no allocation allowed) ----------------
__device__ __align__(256) __half  g_xt[NR * MPAD * DIM];     // 205 MB
__device__ __align__(256) __half  g_ah[MPAD * DIM];          // GEMM A input (x, then h)
__device__ __align__(256) __half  g_bt0[NR * DIM * DIM];
__device__ __align__(256) __half  g_bt1[NR * DIM * DIM];
__device__ int       g_cnt[NN + 1];
__device__ int       g_off[NN + 1];
__device__ int       g_cur[NN];
__device__ unsigned  g_pack[NE];
__device__ int       g_is64_idx;
__device__ int       g_is64_typ;

// ---------------- PTX helpers (base-target only) ----------------
__device__ __forceinline__ uint32_t smem_u32(const void* p) {
    uint32_t a;
    asm("{ .reg .u64 t; cvta.to.shared.u64 t, %1; cvt.u32.u64 %0, t; }" : "=r"(a) : "l"(p));
    return a;
}
__device__ __forceinline__ void cp16(uint32_t dst, const void* src) {
    asm volatile("cp.async.cg.shared.global [%0], [%1], 16;" :: "r"(dst), "l"(src) : "memory");
}
__device__ __forceinline__ void cp_commit() {
    asm volatile("cp.async.commit_group;" ::: "memory");
}
__device__ __forceinline__ void cp_wait1() {
    asm volatile("cp.async.wait_group 1;" ::: "memory");
}
__device__ __forceinline__ void ldsm4(uint32_t* r, uint32_t addr) {
    asm volatile("ldmatrix.sync.aligned.m8n8.x4.shared.b16 {%0,%1,%2,%3}, [%4];"
                 : "=r"(r[0]), "=r"(r[1]), "=r"(r[2]), "=r"(r[3]) : "r"(addr));
}
__device__ __forceinline__ void mma16816(float* d, const uint32_t* a, const uint32_t* b) {
    asm volatile("mma.sync.aligned.m16n8k16.row.col.f32.f16.f16.f32 "
                 "{%0,%1,%2,%3}, {%4,%5,%6,%7}, {%8,%9}, {%0,%1,%2,%3};"
                 : "+f"(d[0]), "+f"(d[1]), "+f"(d[2]), "+f"(d[3])
                 : "r"(a[0]), "r"(a[1]), "r"(a[2]), "r"(a[3]), "r"(b[0]), "r"(b[1]));
}

// ---------------- dtype detection (int64 vs int32 for indices) ----------------
__global__ void detect_kernel(const int* eidx, const int* etyp) {
    if (threadIdx.x == 0 && blockIdx.x == 0) {
        int ok_i = 1, ok_t = 1;
        for (int k = 0; k < 16; k++) {
            if (eidx[2 * k + 1] != 0) ok_i = 0;
            if (etyp[2 * k + 1] != 0) ok_t = 0;
        }
        g_is64_idx = ok_i;
        g_is64_typ = ok_t;
    }
}
__device__ __forceinline__ int ld_idx(const void* p, int i, int is64) {
    return is64 ? (int)((const long long*)p)[i] : ((const int*)p)[i];
}

// ---------------- prep: convert x -> fp16 with zero padding (float4 -> half4) ----------------
__global__ void conv_kernel(const float* __restrict__ src) {
    size_t q = (size_t)blockIdx.x * blockDim.x + threadIdx.x;   // quad index
    if (q >= (size_t)MPAD * DIM / 4) return;
    uint2 outv;
    if (q < (size_t)NN * DIM / 4) {
        float4 v = reinterpret_cast<const float4*>(src)[q];
        __half2 lo = __floats2half2_rn(v.x, v.y);
        __half2 hi = __floats2half2_rn(v.z, v.w);
        outv = make_uint2(*reinterpret_cast<uint32_t*>(&lo), *reinterpret_cast<uint32_t*>(&hi));
    } else {
        outv = make_uint2(0u, 0u);
    }
    reinterpret_cast<uint2*>(g_ah)[q] = outv;
}

// ---------------- prep: transpose W[r,k,n] -> Bt[r,n,k] fp16 ----------------
__global__ void prep_w_kernel(const float* __restrict__ W0, const float* __restrict__ W1) {
    int idx = blockIdx.x * blockDim.x + threadIdx.x;
    if (idx >= NR * DIM * DIM) return;
    int r = idx >> 16, n = (idx >> 8) & 255, k = idx & 255;
    size_t s = ((size_t)r << 16) + (size_t)k * DIM + n;
    g_bt0[idx] = __float2half_rn(W0[s]);
    g_bt1[idx] = __float2half_rn(W1[s]);
}

// ---------------- CSR build ----------------
__global__ void zero_cnt_kernel() {
    int i = blockIdx.x * blockDim.x + threadIdx.x;
    if (i <= NN) g_cnt[i] = 0;
}
__global__ void hist_kernel(const void* eidx) {
    int e = blockIdx.x * blockDim.x + threadIdx.x;
    if (e >= NE) return;
    int dst = ld_idx(eidx, NE + e, g_is64_idx);
    atomicAdd(&g_cnt[dst], 1);
}
__global__ void scan_kernel() {
    __shared__ int part[1024];
    const int t = threadIdx.x;
    const int PER = (NN + 1023) / 1024;   // 49
    const int base = t * PER;
    int sum = 0;
    for (int i = 0; i < PER; i++) {
        int idx = base + i;
        if (idx < NN) sum += g_cnt[idx];
    }
    part[t] = sum;
    __syncthreads();
    int acc = sum;
    for (int o = 1; o < 1024; o <<= 1) {
        int add = (t >= o) ? part[t - o] : 0;
        __syncthreads();
        acc += add;
        part[t] = acc;
        __syncthreads();
    }
    int run = acc - sum;   // exclusive prefix of this thread's chunk
    for (int i = 0; i < PER; i++) {
        int idx = base + i;
        if (idx > NN) break;
        if (idx == NN) { g_off[NN] = run; break; }
        g_off[idx] = run;
        g_cur[idx] = run;
        run += g_cnt[idx];
    }
}
__global__ void fill_kernel(const void* eidx, const void* etyp) {
    int e = blockIdx.x * blockDim.x + threadIdx.x;
    if (e >= NE) return;
    int is64i = g_is64_idx;
    int src = ld_idx(eidx, e, is64i);
    int dst = ld_idx(eidx, NE + e, is64i);
    int rel = ld_idx(etyp, e, g_is64_typ);
    int pos = atomicAdd(&g_cur[dst], 1);
    g_pack[pos] = (unsigned)src | ((unsigned)rel << 16);
}

// ---------------- GEMM: XT[r] = A @ W[r]  (mma.sync fp16, 4 warps of 64x64) ----------------
// grid (MTILES, 2, NR), 128 threads = 4 warps in 2(m) x 2(n). CTA tile 128x128, K=256.
__global__ __launch_bounds__(128, 2) void gemm_kernel(int layer) {
    extern __shared__ char dyn[];
    const int tid  = threadIdx.x;
    const int lane = tid & 31, warp = tid >> 5;
    const int wm = warp >> 1, wn = warp & 1;
    const int mbase = blockIdx.x * 128;
    const int nbase = blockIdx.y * 128;
    const int rel   = blockIdx.z;

    const __half* Bp = (layer ? g_bt1 : g_bt0) + ((size_t)rel << 16) + (size_t)nbase * DIM;
    const __half* Ap = g_ah + (size_t)mbase * DIM;

    const uint32_t sbase = smem_u32(dyn);

    float acc[4][8][4];
    #pragma unroll
    for (int i = 0; i < 4; i++)
        #pragma unroll
        for (int j = 0; j < 8; j++)
            #pragma unroll
            for (int q = 0; q < 4; q++) acc[i][j][q] = 0.f;

    // stage loader: A | B, 128 rows x 64 fp16 each (128 B/row), XOR swizzle on 16B segs
    auto load_stage = [&](int buf, int k0) {
        uint32_t sb = sbase + buf * STAGE_BYTES;
        const __half* srcs[2] = { Ap, Bp };
        #pragma unroll
        for (int arr = 0; arr < 2; arr++) {
            #pragma unroll
            for (int it = 0; it < 8; it++) {
                int rem = tid + it * 128;        // 0..1023
                int row = rem >> 3, seg = rem & 7;
                cp16(sb + arr * AREA + row * 128 + ((seg ^ (row & 7)) << 4),
                     srcs[arr] + (size_t)row * DIM + k0 + seg * 8);
            }
        }
    };

    load_stage(0, 0);  cp_commit();
    load_stage(1, BK); cp_commit();

    #pragma unroll
    for (int s = 0; s < 4; s++) {
        cp_wait1();
        __syncthreads();
        if (s + 2 < 4) load_stage((s + 2) % STAGES, (s + 2) * BK);
        cp_commit();

        uint32_t sb = sbase + (s % STAGES) * STAGE_BYTES;
        #pragma unroll
        for (int k16 = 0; k16 < 4; k16++) {
            uint32_t af[4][4];
            uint32_t bf[8][2];
            #pragma unroll
            for (int mt = 0; mt < 4; mt++) {
                int m_local = wm * 64 + mt * 16 + (lane & 15);
                int seg = k16 * 2 + (lane >> 4);
                ldsm4(af[mt], sb + m_local * 128 + ((seg ^ (m_local & 7)) << 4));
            }
            {
                uint32_t bbase = sb + AREA;
                #pragma unroll
                for (int np = 0; np < 4; np++) {
                    int n_local = wn * 64 + np * 16 + ((lane >> 4) << 3) + (lane & 7);
                    int seg = k16 * 2 + ((lane >> 3) & 1);
                    ldsm4(&bf[np * 2][0], bbase + n_local * 128 + ((seg ^ (n_local & 7)) << 4));
                }
            }
            #pragma unroll
            for (int mt = 0; mt < 4; mt++)
                #pragma unroll
                for (int nt = 0; nt < 8; nt++)
                    mma16816(acc[mt][nt], af[mt], bf[nt]);
        }
    }

    // epilogue: write fp16 tile to g_xt[rel]
    #pragma unroll
    for (int mt = 0; mt < 4; mt++) {
        int gm = mbase + wm * 64 + mt * 16 + (lane >> 2);
        __half* rowp = g_xt + ((size_t)rel * MPAD + gm) * DIM + nbase + wn * 64 + 2 * (lane & 3);
        #pragma unroll
        for (int nt = 0; nt < 8; nt++) {
            __half2 lo = __floats2half2_rn(acc[mt][nt][0], acc[mt][nt][1]);
            __half2 hi = __floats2half2_rn(acc[mt][nt][2], acc[mt][nt][3]);
            *reinterpret_cast<__half2*>(rowp + nt * 8) = lo;
            *reinterpret_cast<__half2*>(rowp + 8 * DIM + nt * 8) = hi;
        }
    }
}

// ---------------- edge aggregation: out[dst] = sum relu(XT[rel,src] + b) ----------------
// warp per dst; lane covers 8 cols (16B fp16). fp32 accumulate. 8-deep MLP gather.
// out_fp32 == nullptr -> write fp16 into g_ah (next layer's GEMM input).
__global__ __launch_bounds__(256) void edge_kernel(const float* __restrict__ bias,
                                                   float* __restrict__ out_fp32) {
    int warp = threadIdx.x >> 5, lane = threadIdx.x & 31;
    int dst = blockIdx.x * 8 + warp;
    if (dst >= NN) return;

    float b[8], acc[8];
    {
        float4 b0 = reinterpret_cast<const float4*>(bias)[lane * 2];
        float4 b1 = reinterpret_cast<const float4*>(bias)[lane * 2 + 1];
        b[0] = b0.x; b[1] = b0.y; b[2] = b0.z; b[3] = b0.w;
        b[4] = b1.x; b[5] = b1.y; b[6] = b1.z; b[7] = b1.w;
    }
    #pragma unroll
    for (int j = 0; j < 8; j++) acc[j] = 0.f;

    int s = g_off[dst], e = g_off[dst + 1];
    const uint4* xt = reinterpret_cast<const uint4*>(g_xt);   // 8 halves per uint4; row = 32 uint4

    auto addv = [&](uint4 v) {
        const __half2* hp = reinterpret_cast<const __half2*>(&v);
        #pragma unroll
        for (int j = 0; j < 4; j++) {
            float2 f = __half22float2(hp[j]);
            acc[2 * j]     += fmaxf(f.x + b[2 * j], 0.f);
            acc[2 * j + 1] += fmaxf(f.y + b[2 * j + 1], 0.f);
        }
    };

    int i = s;
    // 8-deep: issue all pack loads, then all row loads, then consume
    for (; i + 7 < e; i += 8) {
        unsigned p[8];
        #pragma unroll
        for (int j = 0; j < 8; j++) p[j] = __ldg(&g_pack[i + j]);
        uint4 v[8];
        #pragma unroll
        for (int j = 0; j < 8; j++)
            v[j] = __ldg(&xt[((size_t)(p[j] >> 16) * MPAD + (p[j] & 0xFFFFu)) * 32 + lane]);
        #pragma unroll
        for (int j = 0; j < 8; j++) addv(v[j]);
    }
    if (i + 3 < e) {
        unsigned p[4];
        #pragma unroll
        for (int j = 0; j < 4; j++) p[j] = __ldg(&g_pack[i + j]);
        uint4 v[4];
        #pragma unroll
        for (int j = 0; j < 4; j++)
            v[j] = __ldg(&xt[((size_t)(p[j] >> 16) * MPAD + (p[j] & 0xFFFFu)) * 32 + lane]);
        #pragma unroll
        for (int j = 0; j < 4; j++) addv(v[j]);
        i += 4;
    }
    for (; i < e; i++) {
        unsigned p0 = __ldg(&g_pack[i]);
        addv(__ldg(&xt[((size_t)(p0 >> 16) * MPAD + (p0 & 0xFFFFu)) * 32 + lane]));
    }

    if (out_fp32) {
        float4* op = reinterpret_cast<float4*>(out_fp32) + (size_t)dst * 64 + lane * 2;
        op[0] = make_float4(acc[0], acc[1], acc[2], acc[3]);
        op[1] = make_float4(acc[4], acc[5], acc[6], acc[7]);
    } else {
        uint4 ov;
        __half2 h0 = __floats2half2_rn(acc[0], acc[1]);
        __half2 h1 = __floats2half2_rn(acc[2], acc[3]);
        __half2 h2 = __floats2half2_rn(acc[4], acc[5]);
        __half2 h3 = __floats2half2_rn(acc[6], acc[7]);
        ov.x = *reinterpret_cast<uint32_t*>(&h0);
        ov.y = *reinterpret_cast<uint32_t*>(&h1);
        ov.z = *reinterpret_cast<uint32_t*>(&h2);
        ov.w = *reinterpret_cast<uint32_t*>(&h3);
        reinterpret_cast<uint4*>(g_ah)[(size_t)dst * 32 + lane] = ov;
    }
}

// ---------------- launch ----------------
extern "C" void kernel_launch(void* const* d_in, const int* in_sizes, int n_in,
                              void* d_out, int out_size) {
    const float* x  = (const float*)d_in[0];
    const float* W0 = (const float*)d_in[1];
    const float* b0 = (const float*)d_in[2];
    const float* W1 = (const float*)d_in[3];
    const float* b1 = (const float*)d_in[4];
    const void*  ei = d_in[5];
    const void*  et = d_in[6];
    float* out = (float*)d_out;

    cudaFuncSetAttribute(gemm_kernel, cudaFuncAttributeMaxDynamicSharedMemorySize, GEMM_SMEM);

    int conv_blocks = (MPAD * DIM / 4 + 255) / 256;

    // Order chosen so the layer-0 GEMM sits in the ncu profiling window (4th launch)
    detect_kernel<<<1, 32>>>((const int*)ei, (const int*)et);            // 1
    conv_kernel<<<conv_blocks, 256>>>(x);                                // 2
    prep_w_kernel<<<(NR * DIM * DIM + 255) / 256, 256>>>(W0, W1);        // 3
    gemm_kernel<<<dim3(MTILES, 2, NR), 128, GEMM_SMEM>>>(0);             // 4  <- profiled
    zero_cnt_kernel<<<(NN + 256) / 256, 256>>>();                        // 5
    hist_kernel<<<(NE + 255) / 256, 256>>>(ei);                          // 6
    scan_kernel<<<1, 1024>>>();                                          // 7
    fill_kernel<<<(NE + 255) / 256, 256>>>(ei, et);                      // 8

    edge_kernel<<<(NN + 7) / 8, 256>>>(b0, nullptr);                     // -> g_ah (fp16 h)

    // layer 2
    gemm_kernel<<<dim3(MTILES, 2, NR), 128, GEMM_SMEM>>>(1);
    edge_kernel<<<(NN + 7) / 8, 256>>>(b1, out);
}